// round 8
// baseline (speedup 1.0000x reference)
#include <cuda_runtime.h>

typedef unsigned long long u64t;

__device__ __forceinline__ u64t fma2(u64t a, u64t b, u64t c) {
    u64t d;
    asm("fma.rn.f32x2 %0, %1, %2, %3;" : "=l"(d) : "l"(a), "l"(b), "l"(c));
    return d;
}
__device__ __forceinline__ u64t add2(u64t a, u64t b) {
    u64t d;
    asm("add.rn.f32x2 %0, %1, %2;" : "=l"(d) : "l"(a), "l"(b));
    return d;
}
__device__ __forceinline__ u64t pk2(float lo, float hi) {
    u64t d;
    asm("mov.b64 %0, {%1, %2};" : "=l"(d) : "f"(lo), "f"(hi));
    return d;
}
__device__ __forceinline__ void unpk(u64t v, float& lo, float& hi) {
    asm("mov.b64 {%0, %1}, %2;" : "=f"(lo), "=f"(hi) : "l"(v));
}
__device__ __forceinline__ float fsqrt_ap(float x) {
    float y;
    asm("sqrt.approx.f32 %0, %1;" : "=f"(y) : "f"(x));
    return y;
}
__device__ __forceinline__ u64t shx(u64t v, int m) {
    unsigned lo = (unsigned)v, hi = (unsigned)(v >> 32);
    lo = __shfl_xor_sync(0xffffffffu, lo, m);
    hi = __shfl_xor_sync(0xffffffffu, hi, m);
    return ((u64t)hi << 32) | lo;
}
__device__ __forceinline__ u64t quadsum(u64t v) {
    v = add2(v, shx(v, 1));
    v = add2(v, shx(v, 2));
    return v;
}

// ---- weight region (u64t units) ----
// sW1: [24 j][19 k][12]: slots s<8: (q = s>>1, rp = s&1); s>=8: (q = s-8, rp = 2)
//      row pair (6q+2rp, 6q+2rp+1); rows >= 19 are zero pad (rows padded to 24)
// sW2: [24 j][24 k][3 dp]: k<19 real, k=19 = b2 (fed by hs=1 on lane q3), k>=20 zero
// sW0: [288 f'][3 dp]  (columns permuted to f' order)
// sB1: [24 j][12]  (same slot scheme as sW1)
// sB0: [3 dp]
#define OW1 0
#define OW2 5472
#define OW0 7200
#define OB1 8064
#define OB0 8352
#define SM_U64 8356          // 66848 B (16B aligned)

// ---- stash: element-major, 292 floats/element, 128 elements ----
// f' = 12*J + i : i in [0,9) = rot i of joint J ; i in [9,12) = jtr c of joint J
#define ESTRIDE 292
#define STASH_WORDS (128 * ESTRIDE)
#define SMEM_BYTES  (SM_U64 * 8 + STASH_WORDS * 4)   // 216352 B

template<int J, int PS, int WS>
__device__ __forceinline__ void do_joint(
    float* __restrict__ se, int q, const u64t* __restrict__ sm,
    u64t (&fslot)[4][3], float (&jx)[4], float (&jy)[4], float (&jz)[4],
    const u64t (&g)[3])
{
    // 12 inputs of joint J (broadcast across the quad)
    float xs[19];
    {
        const float4* xb = (const float4*)(se + 12*J);
        float4 a = xb[0], b = xb[1], c = xb[2];
        xs[0]=a.x; xs[1]=a.y; xs[2]=a.z; xs[3]=a.w;
        xs[4]=b.x; xs[5]=b.y; xs[6]=b.z; xs[7]=b.w;
        xs[8]=c.x; xs[9]=c.y; xs[10]=c.z; xs[11]=c.w;
    }
    float jxv = xs[9], jyv = xs[10], jzv = xs[11];

    float dx, dy, dz;
    if (PS < 0) { dx = jxv; dy = jyv; dz = jzv; }
    else {
        const int P = (PS < 0) ? 0 : PS;
        dx = jxv - jx[P]; dy = jyv - jy[P]; dz = jzv - jz[P];
    }
    xs[12] = fsqrt_ap(dx*dx + dy*dy + dz*dz);
    jx[WS] = jxv; jy[WS] = jyv; jz[WS] = jzv;

    if (PS < 0) {
        unpk(g[0], xs[13], xs[14]); unpk(g[1], xs[15], xs[16]); unpk(g[2], xs[17], xs[18]);
    } else {
        const int P = (PS < 0) ? 0 : PS;
        unpk(fslot[P][0], xs[13], xs[14]);
        unpk(fslot[P][1], xs[15], xs[16]);
        unpk(fslot[P][2], xs[17], xs[18]);
    }

    // ---- layer 1: this lane's 3 row-pairs (rows 6q .. 6q+5) ----
    u64t h0, h1, h2;
    {
        const u64t* bb = sm + OB1 + J*12;
        ulonglong2 t = *(const ulonglong2*)(bb + 2*q);
        h0 = t.x; h1 = t.y; h2 = bb[8 + q];
    }
    const u64t* wb = sm + OW1 + (J*19)*12;
#pragma unroll
    for (int k = 0; k < 19; ++k) {
        const u64t* wr = wb + k*12;
        ulonglong2 w01 = *(const ulonglong2*)(wr + 2*q);
        u64t w2 = wr[8 + q];
        u64t xx = pk2(xs[k], xs[k]);
        h0 = fma2(xx, w01.x, h0);
        h1 = fma2(xx, w01.y, h1);
        h2 = fma2(xx, w2,    h2);
    }

    // relu -> 6 local h scalars (layer-2 k-range 6q .. 6q+5)
    float hs[6];
    { float a, b; unpk(h0, a, b); hs[0] = fmaxf(a, 0.f); hs[1] = fmaxf(b, 0.f); }
    { float a, b; unpk(h1, a, b); hs[2] = fmaxf(a, 0.f); hs[3] = fmaxf(b, 0.f); }
    { float a, b; unpk(h2, a, b); hs[4] = fmaxf(a, 0.f); hs[5] = fmaxf(b, 0.f); }
    if (q == 3) hs[1] = 1.0f;     // global row 19 -> feeds b2 row (k=19) of sW2

    // ---- layer 2 partial over k = 6q .. 6q+5 ----
    u64t o0 = 0ull, o1 = 0ull, o2 = 0ull;
#pragma unroll
    for (int i = 0; i < 3; ++i) {
        int k0 = 6*q + 2*i;
        const u64t* wp = sm + OW2 + (J*24 + k0)*3;
        ulonglong2 p01 = *(const ulonglong2*)wp;
        u64t p2 = wp[2];
        ulonglong2 p34 = *(const ulonglong2*)(wp + 3);   // next k row, first 2
        u64t p5 = wp[5];
        u64t x0 = pk2(hs[2*i],   hs[2*i]);
        u64t x1 = pk2(hs[2*i+1], hs[2*i+1]);
        o0 = fma2(x0, p01.x, o0);
        o1 = fma2(x0, p01.y, o1);
        o2 = fma2(x0, p2,    o2);
        o0 = fma2(x1, p34.x, o0);
        o1 = fma2(x1, p34.y, o1);
        o2 = fma2(x1, p5,    o2);
    }
    // quad reduction -> all 4 lanes hold the full 6 outputs
    o0 = quadsum(o0);
    o1 = quadsum(o1);
    o2 = quadsum(o2);

    fslot[WS][0] = o0; fslot[WS][1] = o1; fslot[WS][2] = o2;

    // write outputs into freed rot slots f' = 12J .. 12J+5 (one st.64 per lane)
    u64t* dst = (u64t*)(se + 12*J);
    if (q == 0) dst[0] = o0;
    else if (q == 1) dst[1] = o1;
    else if (q == 2) dst[2] = o2;
}

__global__ void __launch_bounds__(512, 1)
pose_kernel(const float* __restrict__ rots, const float* __restrict__ jtrs,
            const float* __restrict__ W0, const float* __restrict__ b0,
            const float* __restrict__ W1, const float* __restrict__ b1,
            const float* __restrict__ W2, const float* __restrict__ b2,
            float* __restrict__ out)
{
    extern __shared__ u64t sm[];
    float* stash = (float*)(sm + SM_U64);
    const int tid = threadIdx.x;

    // ---- staging: coalesced LDG.128 -> contiguous STS (f' interleaved layout) ----
    {
        const float4* gr4 = (const float4*)(rots + (size_t)blockIdx.x * 128 * 216);
        const float4* gt4 = (const float4*)(jtrs + (size_t)blockIdx.x * 128 * 72);
#pragma unroll
        for (int i = 0; i < 14; ++i) {                  // rots: 6912 float4
            int G = i*512 + tid;
            if (i < 13 || G < 6912) {
                float4 v = gr4[G];
                int e = G / 54, f4 = G % 54;
                float* dst = stash + e*ESTRIDE;
                int fo = 4*f4;
                float vv[4] = {v.x, v.y, v.z, v.w};
#pragma unroll
                for (int c = 0; c < 4; ++c) {
                    int f = fo + c;
                    int Jc = f / 9;                     // f' = f + 3*Jc
                    dst[f + 3*Jc] = vv[c];
                }
            }
        }
#pragma unroll
        for (int i = 0; i < 5; ++i) {                   // jtrs: 2304 float4
            int G = i*512 + tid;
            if (i < 4 || G < 2304) {
                float4 v = gt4[G];
                int e = G / 18, f4 = G % 18;
                float* dst = stash + e*ESTRIDE;
                int mo = 4*f4;
                float vv[4] = {v.x, v.y, v.z, v.w};
#pragma unroll
                for (int c = 0; c < 4; ++c) {
                    int m = mo + c;
                    int Jt = m / 3;                     // f' = m + 9*Jt + 9
                    dst[m + 9*Jt + 9] = vv[c];
                }
            }
        }
    }

    // ---- weight packing ----
    for (int i = tid; i < 24*19*12; i += 512) {
        int s = i % 12; int t = i / 12; int k = t % 19; int j = t / 19;
        int qq = (s < 8) ? (s >> 1) : (s - 8);
        int rp = (s < 8) ? (s & 1)  : 2;
        int r = 6*qq + 2*rp;
        float lo = (r     < 19) ? W1[(j*19 + r    )*19 + k] : 0.f;
        float hi = (r + 1 < 19) ? W1[(j*19 + r + 1)*19 + k] : 0.f;
        sm[OW1 + i] = pk2(lo, hi);
    }
    for (int i = tid; i < 24*24*3; i += 512) {
        int dp = i % 3; int t = i / 3; int k = t % 24; int j = t / 24;
        float lo = 0.f, hi = 0.f;
        if (k < 19)      { lo = W2[(j*6 + 2*dp)*19 + k]; hi = W2[(j*6 + 2*dp + 1)*19 + k]; }
        else if (k == 19){ lo = b2[j*6 + 2*dp];          hi = b2[j*6 + 2*dp + 1]; }
        sm[OW2 + i] = pk2(lo, hi);
    }
    for (int i = tid; i < 288*3; i += 512) {            // W0 columns permuted to f' order
        int dp = i % 3; int fp = i / 3;
        int J = fp / 12, ii = fp % 12;
        int f = (ii < 9) ? (9*J + ii) : (216 + 3*J + (ii - 9));
        sm[OW0 + i] = pk2(W0[(2*dp)*288 + f], W0[(2*dp + 1)*288 + f]);
    }
    for (int i = tid; i < 24*12; i += 512) {
        int s = i % 12; int j = i / 12;
        int qq = (s < 8) ? (s >> 1) : (s - 8);
        int rp = (s < 8) ? (s & 1)  : 2;
        int r = 6*qq + 2*rp;
        float lo = (r     < 19) ? b1[j*19 + r    ] : 0.f;
        float hi = (r + 1 < 19) ? b1[j*19 + r + 1] : 0.f;
        sm[OB1 + i] = pk2(lo, hi);
    }
    if (tid < 3) sm[OB0 + tid] = pk2(b0[2*tid], b0[2*tid + 1]);
    __syncthreads();

    const int e = tid >> 2;        // element owned by this lane quad
    const int q = tid & 3;         // quarter of rows / k-range
    float* se = stash + e*ESTRIDE;

    // ---- pass 1: gfeat partial over f' = 72q .. 72q+71, then quad reduce ----
    u64t g[3];
    if (q == 0) { g[0] = sm[OB0 + 0]; g[1] = sm[OB0 + 1]; g[2] = sm[OB0 + 2]; }
    else        { g[0] = 0ull;        g[1] = 0ull;        g[2] = 0ull; }
    {
        const int koff = 72 * q;
        const float4* xb = (const float4*)(se + koff);
#pragma unroll 3
        for (int qq = 0; qq < 18; ++qq) {               // 4 features per iter
            float4 xv = xb[qq];
            float vv[4] = {xv.x, xv.y, xv.z, xv.w};
#pragma unroll
            for (int cp = 0; cp < 2; ++cp) {
                int k0 = koff + 4*qq + 2*cp;
                const u64t* wp = sm + OW0 + k0*3;
                ulonglong2 p01 = *(const ulonglong2*)wp;
                u64t p2 = wp[2];
                ulonglong2 p34 = *(const ulonglong2*)(wp + 3);
                u64t p5 = wp[5];
                u64t x0 = pk2(vv[2*cp],   vv[2*cp]);
                u64t x1 = pk2(vv[2*cp+1], vv[2*cp+1]);
                g[0] = fma2(x0, p01.x, g[0]);
                g[1] = fma2(x0, p01.y, g[1]);
                g[2] = fma2(x0, p2,    g[2]);
                g[0] = fma2(x1, p34.x, g[0]);
                g[1] = fma2(x1, p34.y, g[1]);
                g[2] = fma2(x1, p5,    g[2]);
            }
        }
    }
    g[0] = quadsum(g[0]);
    g[1] = quadsum(g[1]);
    g[2] = quadsum(g[2]);

    // ---- pass 2: joint chain ----
    u64t fslot[4][3];
    float jx[4], jy[4], jz[4];

    do_joint< 0,-1,0>(se, q, sm, fslot, jx, jy, jz, g);
    do_joint< 1, 0,1>(se, q, sm, fslot, jx, jy, jz, g);
    do_joint< 2, 0,2>(se, q, sm, fslot, jx, jy, jz, g);
    do_joint< 3, 0,3>(se, q, sm, fslot, jx, jy, jz, g);
    do_joint< 4, 1,0>(se, q, sm, fslot, jx, jy, jz, g);
    do_joint< 5, 2,1>(se, q, sm, fslot, jx, jy, jz, g);
    do_joint< 6, 3,2>(se, q, sm, fslot, jx, jy, jz, g);
    do_joint< 7, 0,3>(se, q, sm, fslot, jx, jy, jz, g);
    do_joint< 8, 1,0>(se, q, sm, fslot, jx, jy, jz, g);
    do_joint< 9, 2,1>(se, q, sm, fslot, jx, jy, jz, g);
    do_joint<10, 3,2>(se, q, sm, fslot, jx, jy, jz, g);
    do_joint<11, 0,2>(se, q, sm, fslot, jx, jy, jz, g);
    do_joint<12, 1,2>(se, q, sm, fslot, jx, jy, jz, g);
    do_joint<13, 1,0>(se, q, sm, fslot, jx, jy, jz, g);
    do_joint<14, 1,3>(se, q, sm, fslot, jx, jy, jz, g);
    do_joint<15, 2,1>(se, q, sm, fslot, jx, jy, jz, g);
    do_joint<16, 0,1>(se, q, sm, fslot, jx, jy, jz, g);
    do_joint<17, 3,0>(se, q, sm, fslot, jx, jy, jz, g);
    do_joint<18, 1,3>(se, q, sm, fslot, jx, jy, jz, g);
    do_joint<19, 0,1>(se, q, sm, fslot, jx, jy, jz, g);
    do_joint<20, 3,0>(se, q, sm, fslot, jx, jy, jz, g);
    do_joint<21, 1,3>(se, q, sm, fslot, jx, jy, jz, g);
    do_joint<22, 0,1>(se, q, sm, fslot, jx, jy, jz, g);
    do_joint<23, 3,0>(se, q, sm, fslot, jx, jy, jz, g);

    // ---- epilogue: coalesced store of all 128 x 144 outputs ----
    __syncthreads();
    float* og = out + (size_t)blockIdx.x * (128 * 144);
#pragma unroll 6
    for (int i = 0; i < 36; ++i) {
        int G = i*512 + tid;
        int ee = G / 144, p = G % 144;
        int J = p / 6;                                  // f' = p + 6J
        og[G] = stash[ee*ESTRIDE + p + 6*J];
    }
}

extern "C" void kernel_launch(void* const* d_in, const int* in_sizes, int n_in,
                              void* d_out, int out_size) {
    (void)n_in; (void)out_size;
    const float* rots = (const float*)d_in[0];
    const float* jtrs = (const float*)d_in[1];
    const float* W0   = (const float*)d_in[2];
    const float* b0   = (const float*)d_in[3];
    const float* W1   = (const float*)d_in[4];
    const float* b1   = (const float*)d_in[5];
    const float* W2   = (const float*)d_in[6];
    const float* b2   = (const float*)d_in[7];
    float* out = (float*)d_out;

    int n = in_sizes[0] / 216;        // B (131072 -> divisible by 128)
    int grid = n / 128;

    cudaFuncSetAttribute(pose_kernel, cudaFuncAttributeMaxDynamicSharedMemorySize, SMEM_BYTES);
    pose_kernel<<<grid, 512, SMEM_BYTES>>>(rots, jtrs, W0, b0, W1, b1, W2, b2, out);
}

// round 9
// speedup vs baseline: 1.5165x; 1.5165x over previous
#include <cuda_runtime.h>

typedef unsigned long long u64t;

__device__ __forceinline__ u64t fma2(u64t a, u64t b, u64t c) {
    u64t d;
    asm("fma.rn.f32x2 %0, %1, %2, %3;" : "=l"(d) : "l"(a), "l"(b), "l"(c));
    return d;
}
__device__ __forceinline__ u64t add2(u64t a, u64t b) {
    u64t d;
    asm("add.rn.f32x2 %0, %1, %2;" : "=l"(d) : "l"(a), "l"(b));
    return d;
}
__device__ __forceinline__ u64t pk2(float lo, float hi) {
    u64t d;
    asm("mov.b64 %0, {%1, %2};" : "=l"(d) : "f"(lo), "f"(hi));
    return d;
}
__device__ __forceinline__ void unpk(u64t v, float& lo, float& hi) {
    asm("mov.b64 {%0, %1}, %2;" : "=f"(lo), "=f"(hi) : "l"(v));
}
__device__ __forceinline__ float fsqrt_ap(float x) {
    float y;
    asm("sqrt.approx.f32 %0, %1;" : "=f"(y) : "f"(x));
    return y;
}
__device__ __forceinline__ u64t shx1(u64t v) {
    unsigned lo = (unsigned)v, hi = (unsigned)(v >> 32);
    lo = __shfl_xor_sync(0xffffffffu, lo, 1);
    hi = __shfl_xor_sync(0xffffffffu, hi, 1);
    return ((u64t)hi << 32) | lo;
}

// ---- weight region (u64t units) ----
// sW1: [24][19 k][12]: slots 0..4 = row-pairs 0..4 (rows 0..9), slot 5 pad,
//                      slots 6..10 = row-pairs 5..9 (pair 9 hi = 0 pad), slot 11 pad
// sW2: [24][20 k][3 dp]  (k=19 row = b2; fed by hs==1 on odd lane)
// sW0: [288 f'][3 dp]    (columns PERMUTED to f' order)
// sB1: [24][12] (same half scheme as sW1)
// sB0: [3 dp]
#define OW1 0
#define OW2 5472
#define OW0 6912
#define OB1 7776
#define OB0 8064
#define SM_U64 8068            // 64544 B

// ---- stash: element-major, stride 292 floats/element ----
// f' = 12*J + i : i in [0,9) = rot i of joint J ; i in [9,12) = jtr c of joint J
#define ESTRIDE 292
#define STASH_WORDS (128 * ESTRIDE)
#define SMEM_BYTES  (SM_U64 * 8 + STASH_WORDS * 4)    // 214048 B

template<int J, int PS, int WS>
__device__ __forceinline__ void do_joint(
    float* __restrict__ se, int half, const u64t* __restrict__ sm,
    u64t (&fslot)[4][3], float (&jx)[4], float (&jy)[4], float (&jz)[4],
    const u64t (&g)[3])
{
    // kick off layer-1 weight prefetch (3 deep) BEFORE the xs gather,
    // so weight latency overlaps the xs loads + bone-length MUFU.
    const u64t* wb = sm + OW1 + (J*19)*12 + half*6;
    ulonglong2 A0 = *(const ulonglong2*)(wb);
    ulonglong2 A1 = *(const ulonglong2*)(wb + 2);
    u64t       A2 = wb[4];
    ulonglong2 B0 = *(const ulonglong2*)(wb + 12);
    ulonglong2 B1 = *(const ulonglong2*)(wb + 14);
    u64t       B2 = wb[16];
    ulonglong2 C0 = *(const ulonglong2*)(wb + 24);
    ulonglong2 C1 = *(const ulonglong2*)(wb + 26);
    u64t       C2 = wb[28];

    // 12 inputs of joint J: one aligned block
    float xs[19];
    {
        const float4* xb = (const float4*)(se + 12*J);
        float4 a = xb[0], b = xb[1], c = xb[2];
        xs[0]=a.x; xs[1]=a.y; xs[2]=a.z; xs[3]=a.w;
        xs[4]=b.x; xs[5]=b.y; xs[6]=b.z; xs[7]=b.w;
        xs[8]=c.x; xs[9]=c.y; xs[10]=c.z; xs[11]=c.w;
    }
    float jxv = xs[9], jyv = xs[10], jzv = xs[11];

    float dx, dy, dz;
    if (PS < 0) { dx = jxv; dy = jyv; dz = jzv; }
    else {
        const int P = (PS < 0) ? 0 : PS;
        dx = jxv - jx[P]; dy = jyv - jy[P]; dz = jzv - jz[P];
    }
    xs[12] = fsqrt_ap(dx*dx + dy*dy + dz*dz);
    jx[WS] = jxv; jy[WS] = jyv; jz[WS] = jzv;

    if (PS < 0) {
        unpk(g[0], xs[13], xs[14]); unpk(g[1], xs[15], xs[16]); unpk(g[2], xs[17], xs[18]);
    } else {
        const int P = (PS < 0) ? 0 : PS;
        unpk(fslot[P][0], xs[13], xs[14]);
        unpk(fslot[P][1], xs[15], xs[16]);
        unpk(fslot[P][2], xs[17], xs[18]);
    }

    // ---- layer 1, this lane's half: 5 row-pair chains, 3-deep weight pipeline ----
    u64t h[5];
    {
        const u64t* bb = sm + OB1 + J*12 + half*6;
        ulonglong2 t0 = *(const ulonglong2*)bb;
        ulonglong2 t1 = *(const ulonglong2*)(bb + 2);
        h[0] = t0.x; h[1] = t0.y; h[2] = t1.x; h[3] = t1.y; h[4] = bb[4];
    }
#pragma unroll
    for (int k = 0; k < 19; ++k) {
        u64t xx = pk2(xs[k], xs[k]);
        ulonglong2 w0, w1; u64t w2;
        if (k % 3 == 0) {
            w0 = A0; w1 = A1; w2 = A2;
            if (k + 3 < 19) {
                const u64t* nx = wb + (k + 3)*12;
                A0 = *(const ulonglong2*)nx; A1 = *(const ulonglong2*)(nx + 2); A2 = nx[4];
            }
        } else if (k % 3 == 1) {
            w0 = B0; w1 = B1; w2 = B2;
            if (k + 3 < 19) {
                const u64t* nx = wb + (k + 3)*12;
                B0 = *(const ulonglong2*)nx; B1 = *(const ulonglong2*)(nx + 2); B2 = nx[4];
            }
        } else {
            w0 = C0; w1 = C1; w2 = C2;
            if (k + 3 < 19) {
                const u64t* nx = wb + (k + 3)*12;
                C0 = *(const ulonglong2*)nx; C1 = *(const ulonglong2*)(nx + 2); C2 = nx[4];
            }
        }
        h[0] = fma2(xx, w0.x, h[0]);
        h[1] = fma2(xx, w0.y, h[1]);
        h[2] = fma2(xx, w1.x, h[2]);
        h[3] = fma2(xx, w1.y, h[3]);
        h[4] = fma2(xx, w2,   h[4]);
    }

    // ---- layer 2: preload the half's 30 contiguous u64 weights, then FMA burst ----
    ulonglong2 wz[15];
    {
        const ulonglong2* wp = (const ulonglong2*)(sm + OW2 + (J*20 + 10*half)*3);
#pragma unroll
        for (int i = 0; i < 15; ++i) wz[i] = wp[i];
    }

    float hs[10];
#pragma unroll
    for (int r = 0; r < 5; ++r) {
        float a, b; unpk(h[r], a, b);
        hs[2*r]   = fmaxf(a, 0.f);
        hs[2*r+1] = fmaxf(b, 0.f);
    }
    if (half) hs[9] = 1.0f;   // row 19 pad -> feeds b2 row (k=19) of sW2

    u64t o0 = 0ull, o1 = 0ull, o2 = 0ull;
#pragma unroll
    for (int i = 0; i < 5; ++i) {
        u64t x0 = pk2(hs[2*i],   hs[2*i]);
        u64t x1 = pk2(hs[2*i+1], hs[2*i+1]);
        // u64 indices 6i .. 6i+5 inside wz
        o0 = fma2(x0, wz[3*i  ].x, o0);
        o1 = fma2(x0, wz[3*i  ].y, o1);
        o2 = fma2(x0, wz[3*i+1].x, o2);
        o0 = fma2(x1, wz[3*i+1].y, o0);
        o1 = fma2(x1, wz[3*i+2].x, o1);
        o2 = fma2(x1, wz[3*i+2].y, o2);
    }
    o0 = add2(o0, shx1(o0));
    o1 = add2(o1, shx1(o1));
    o2 = add2(o2, shx1(o2));

    fslot[WS][0] = o0; fslot[WS][1] = o1; fslot[WS][2] = o2;

    float v0, v1, v2, v3, v4, v5;
    unpk(o0, v0, v1); unpk(o1, v2, v3); unpk(o2, v4, v5);
    float w0s = half ? v3 : v0;
    float w1s = half ? v4 : v1;
    float w2s = half ? v5 : v2;
    float* dst = se + 12*J + 3*half;
    dst[0] = w0s; dst[1] = w1s; dst[2] = w2s;
}

__global__ void __launch_bounds__(256, 1)
pose_kernel(const float* __restrict__ rots, const float* __restrict__ jtrs,
            const float* __restrict__ W0, const float* __restrict__ b0,
            const float* __restrict__ W1, const float* __restrict__ b1,
            const float* __restrict__ W2, const float* __restrict__ b2,
            float* __restrict__ out)
{
    extern __shared__ u64t sm[];
    float* stash = (float*)(sm + SM_U64);
    const int tid = threadIdx.x;

    // ---- staging: coalesced LDG.128 -> contiguous STS (f' interleaved layout) ----
    {
        const float4* gr4 = (const float4*)(rots + (size_t)blockIdx.x * 128 * 216);
        const float4* gt4 = (const float4*)(jtrs + (size_t)blockIdx.x * 128 * 72);
#pragma unroll 3
        for (int i = 0; i < 27; ++i) {                  // rots: 6912 float4
            int G = i*256 + tid;
            float4 v = gr4[G];
            int e = G / 54, f4 = G % 54;
            float* dst = stash + e*ESTRIDE;
            int fo = 4*f4;
            float vv[4] = {v.x, v.y, v.z, v.w};
#pragma unroll
            for (int c = 0; c < 4; ++c) {
                int f = fo + c;
                int Jc = f / 9;                         // f' = f + 3*Jc
                dst[f + 3*Jc] = vv[c];
            }
        }
#pragma unroll 3
        for (int i = 0; i < 9; ++i) {                   // jtrs: 2304 float4
            int G = i*256 + tid;
            float4 v = gt4[G];
            int e = G / 18, f4 = G % 18;
            float* dst = stash + e*ESTRIDE;
            int mo = 4*f4;
            float vv[4] = {v.x, v.y, v.z, v.w};
#pragma unroll
            for (int c = 0; c < 4; ++c) {
                int m = mo + c;
                int Jt = m / 3;                         // f' = m + 9*Jt + 9
                dst[m + 9*Jt + 9] = vv[c];
            }
        }
    }

    // ---- weight packing ----
    for (int i = tid; i < 24*19*12; i += 256) {
        int s = i % 12; int t = i / 12; int k = t % 19; int j = t / 19;
        float lo = 0.f, hi = 0.f;
        int p = (s < 6) ? s : (s - 6 + 5);     // slot -> row pair (5 = pad slot)
        if (s != 5 && s != 11) {
            int r = 2*p;
            lo = W1[(j*19 + r)*19 + k];
            hi = (r + 1 < 19) ? W1[(j*19 + r + 1)*19 + k] : 0.f;
        }
        sm[OW1 + i] = pk2(lo, hi);
    }
    for (int i = tid; i < 24*20*3; i += 256) {
        int dp = i % 3; int t = i / 3; int k = t % 20; int j = t / 20;
        float lo, hi;
        if (k < 19) { lo = W2[(j*6 + 2*dp)*19 + k]; hi = W2[(j*6 + 2*dp + 1)*19 + k]; }
        else        { lo = b2[j*6 + 2*dp];          hi = b2[j*6 + 2*dp + 1]; }
        sm[OW2 + i] = pk2(lo, hi);
    }
    for (int i = tid; i < 288*3; i += 256) {            // W0 columns permuted to f' order
        int dp = i % 3; int fp = i / 3;
        int J = fp / 12, ii = fp % 12;
        int f = (ii < 9) ? (9*J + ii) : (216 + 3*J + (ii - 9));
        sm[OW0 + i] = pk2(W0[(2*dp)*288 + f], W0[(2*dp + 1)*288 + f]);
    }
    for (int i = tid; i < 24*12; i += 256) {
        int s = i % 12; int j = i / 12;
        float lo = 0.f, hi = 0.f;
        int p = (s < 6) ? s : (s - 6 + 5);
        if (s != 5 && s != 11) {
            int r = 2*p;
            lo = b1[j*19 + r];
            hi = (r + 1 < 19) ? b1[j*19 + r + 1] : 0.f;
        }
        sm[OB1 + i] = pk2(lo, hi);
    }
    if (tid < 3) sm[OB0 + tid] = pk2(b0[2*tid], b0[2*tid + 1]);
    __syncthreads();

    const int e    = tid >> 1;
    const int half = tid & 1;
    float* se = stash + e*ESTRIDE;

    // ---- pass 1: gfeat partial over this lane's f' half, double-buffered ----
    u64t g[3];
    if (half == 0) { g[0] = sm[OB0 + 0]; g[1] = sm[OB0 + 1]; g[2] = sm[OB0 + 2]; }
    else           { g[0] = 0ull;        g[1] = 0ull;        g[2] = 0ull; }
    {
        const int koff = half * 144;
        const float4* xb = (const float4*)(se + koff);
        const ulonglong2* wp = (const ulonglong2*)(sm + OW0 + koff*3);

        float4 xcur = xb[0];
        ulonglong2 P0 = wp[0], P1 = wp[1], P2 = wp[2], P3 = wp[3], P4 = wp[4], P5 = wp[5];
#pragma unroll 4
        for (int q = 0; q < 36; ++q) {
            float4 xnext;
            ulonglong2 N0, N1, N2, N3, N4, N5;
            if (q < 35) {
                xnext = xb[q + 1];
                const ulonglong2* np = wp + (q + 1)*6;
                N0 = np[0]; N1 = np[1]; N2 = np[2]; N3 = np[3]; N4 = np[4]; N5 = np[5];
            }
            float vv[4] = {xcur.x, xcur.y, xcur.z, xcur.w};
            {
                u64t x0 = pk2(vv[0], vv[0]);
                u64t x1 = pk2(vv[1], vv[1]);
                g[0] = fma2(x0, P0.x, g[0]);
                g[1] = fma2(x0, P0.y, g[1]);
                g[2] = fma2(x0, P1.x, g[2]);
                g[0] = fma2(x1, P1.y, g[0]);
                g[1] = fma2(x1, P2.x, g[1]);
                g[2] = fma2(x1, P2.y, g[2]);
            }
            {
                u64t x0 = pk2(vv[2], vv[2]);
                u64t x1 = pk2(vv[3], vv[3]);
                g[0] = fma2(x0, P3.x, g[0]);
                g[1] = fma2(x0, P3.y, g[1]);
                g[2] = fma2(x0, P4.x, g[2]);
                g[0] = fma2(x1, P4.y, g[0]);
                g[1] = fma2(x1, P5.x, g[1]);
                g[2] = fma2(x1, P5.y, g[2]);
            }
            if (q < 35) {
                xcur = xnext;
                P0 = N0; P1 = N1; P2 = N2; P3 = N3; P4 = N4; P5 = N5;
            }
        }
    }
    g[0] = add2(g[0], shx1(g[0]));
    g[1] = add2(g[1], shx1(g[1]));
    g[2] = add2(g[2], shx1(g[2]));

    // ---- pass 2: joint chain ----
    u64t fslot[4][3];
    float jx[4], jy[4], jz[4];

    do_joint< 0,-1,0>(se, half, sm, fslot, jx, jy, jz, g);
    do_joint< 1, 0,1>(se, half, sm, fslot, jx, jy, jz, g);
    do_joint< 2, 0,2>(se, half, sm, fslot, jx, jy, jz, g);
    do_joint< 3, 0,3>(se, half, sm, fslot, jx, jy, jz, g);
    do_joint< 4, 1,0>(se, half, sm, fslot, jx, jy, jz, g);
    do_joint< 5, 2,1>(se, half, sm, fslot, jx, jy, jz, g);
    do_joint< 6, 3,2>(se, half, sm, fslot, jx, jy, jz, g);
    do_joint< 7, 0,3>(se, half, sm, fslot, jx, jy, jz, g);
    do_joint< 8, 1,0>(se, half, sm, fslot, jx, jy, jz, g);
    do_joint< 9, 2,1>(se, half, sm, fslot, jx, jy, jz, g);
    do_joint<10, 3,2>(se, half, sm, fslot, jx, jy, jz, g);
    do_joint<11, 0,2>(se, half, sm, fslot, jx, jy, jz, g);
    do_joint<12, 1,2>(se, half, sm, fslot, jx, jy, jz, g);
    do_joint<13, 1,0>(se, half, sm, fslot, jx, jy, jz, g);
    do_joint<14, 1,3>(se, half, sm, fslot, jx, jy, jz, g);
    do_joint<15, 2,1>(se, half, sm, fslot, jx, jy, jz, g);
    do_joint<16, 0,1>(se, half, sm, fslot, jx, jy, jz, g);
    do_joint<17, 3,0>(se, half, sm, fslot, jx, jy, jz, g);
    do_joint<18, 1,3>(se, half, sm, fslot, jx, jy, jz, g);
    do_joint<19, 0,1>(se, half, sm, fslot, jx, jy, jz, g);
    do_joint<20, 3,0>(se, half, sm, fslot, jx, jy, jz, g);
    do_joint<21, 1,3>(se, half, sm, fslot, jx, jy, jz, g);
    do_joint<22, 0,1>(se, half, sm, fslot, jx, jy, jz, g);
    do_joint<23, 3,0>(se, half, sm, fslot, jx, jy, jz, g);

    // ---- epilogue: coalesced store of all 128 x 144 outputs ----
    __syncthreads();
    float* og = out + (size_t)blockIdx.x * (128 * 144);
#pragma unroll 8
    for (int i = 0; i < 72; ++i) {
        int G = i*256 + tid;
        int ee = G / 144, q = G % 144;
        int J = q / 6;                                  // f' = q + 6J
        og[G] = stash[ee*ESTRIDE + q + 6*J];
    }
}

extern "C" void kernel_launch(void* const* d_in, const int* in_sizes, int n_in,
                              void* d_out, int out_size) {
    (void)n_in; (void)out_size;
    const float* rots = (const float*)d_in[0];
    const float* jtrs = (const float*)d_in[1];
    const float* W0   = (const float*)d_in[2];
    const float* b0   = (const float*)d_in[3];
    const float* W1   = (const float*)d_in[4];
    const float* b1   = (const float*)d_in[5];
    const float* W2   = (const float*)d_in[6];
    const float* b2   = (const float*)d_in[7];
    float* out = (float*)d_out;

    int n = in_sizes[0] / 216;        // B (131072 -> divisible by 128)
    int grid = n / 128;

    cudaFuncSetAttribute(pose_kernel, cudaFuncAttributeMaxDynamicSharedMemorySize, SMEM_BYTES);
    pose_kernel<<<grid, 256, SMEM_BYTES>>>(rots, jtrs, W0, b0, W1, b1, W2, b2, out);
}